// round 5
// baseline (speedup 1.0000x reference)
#include <cuda_runtime.h>
#include <cuda_bf16.h>
#include <math.h>

// ---------------------------------------------------------------------------
// Problem constants
// ---------------------------------------------------------------------------
#define FEAT     128
#define FEAT3    384
#define NRBF     20
#define MAXNODES 20000

__device__ float g_h  [MAXNODES * FEAT];
__device__ float g_inv[MAXNODES * FEAT3];
__device__ int   g_nbrs_is64;   // 1 if nbrs buffer is int64, 0 if int32

// ---------------------------------------------------------------------------
// packed f32x2 helpers
// ---------------------------------------------------------------------------
__device__ __forceinline__ void fma2(unsigned long long &acc,
                                     unsigned long long a,
                                     unsigned long long b) {
    asm("fma.rn.f32x2 %0, %1, %2, %0;" : "+l"(acc) : "l"(a), "l"(b));
}
__device__ __forceinline__ unsigned long long pack_dup(float x) {
    unsigned long long p;
    asm("mov.b64 %0, {%1, %1};" : "=l"(p) : "f"(x));
    return p;
}
__device__ __forceinline__ unsigned long long pack2(float x, float y) {
    unsigned long long p;
    asm("mov.b64 %0, {%1, %2};" : "=l"(p) : "f"(x), "f"(y));
    return p;
}
__device__ __forceinline__ void unpack2(unsigned long long p, float &x, float &y) {
    asm("mov.b64 {%0, %1}, %2;" : "=f"(x), "=f"(y) : "l"(p));
}

// ---------------------------------------------------------------------------
// nbrs dtype detector (int64 layout has all-zero odd u32 words)
// ---------------------------------------------------------------------------
__global__ void detect_nbrs_kernel(const unsigned int* __restrict__ p, int n_words)
{
    if (threadIdx.x == 0 && blockIdx.x == 0) {
        unsigned int acc = 0;
        int lim = n_words < 512 ? n_words : 512;
        for (int i = 1; i < lim; i += 2) acc |= p[i];
        g_nbrs_is64 = (acc == 0u) ? 1 : 0;
    }
}

// ---------------------------------------------------------------------------
// SGEMM (R3 version — known good): C = A@B + bias (optional silu)
// BM=128 BN=128 BK=16, 256 threads, TM=8 TN=8, f32x2 accumulators
// ---------------------------------------------------------------------------
#define BM 128
#define BN 128
#define BK 16

__global__ __launch_bounds__(256) void sgemm_kernel(
    const float* __restrict__ A, const float* __restrict__ B,
    const float* __restrict__ bias, float* __restrict__ C,
    int M, int N, int K, int act)
{
    __shared__ __align__(16) float As[BK][BM + 4];
    __shared__ __align__(16) float Bs[BK][BN + 4];

    const int tid  = threadIdx.x;
    const int tx   = tid & 15;
    const int ty   = tid >> 4;
    const int row0 = blockIdx.x * BM;
    const int col0 = blockIdx.y * BN;

    unsigned long long acc[8][4];
    #pragma unroll
    for (int i = 0; i < 8; i++)
        #pragma unroll
        for (int j = 0; j < 4; j++) acc[i][j] = 0ull;

    for (int kk = 0; kk < K; kk += BK) {
        #pragma unroll
        for (int s = 0; s < 2; s++) {
            int f  = tid + s * 256;
            int r  = f >> 2;
            int kq = (f & 3) * 4;
            float4 v = make_float4(0.f, 0.f, 0.f, 0.f);
            if (row0 + r < M)
                v = *(const float4*)&A[(size_t)(row0 + r) * K + kk + kq];
            As[kq + 0][r] = v.x; As[kq + 1][r] = v.y;
            As[kq + 2][r] = v.z; As[kq + 3][r] = v.w;
        }
        #pragma unroll
        for (int s = 0; s < 2; s++) {
            int f  = tid + s * 256;
            int kr = f >> 5;
            int nq = (f & 31) * 4;
            float4 v = *(const float4*)&B[(size_t)(kk + kr) * N + col0 + nq];
            *(float4*)&Bs[kr][nq] = v;
        }
        __syncthreads();

        #pragma unroll
        for (int k = 0; k < BK; k++) {
            float4 a0 = *(const float4*)&As[k][ty * 8];
            float4 a1 = *(const float4*)&As[k][ty * 8 + 4];
            ulonglong2 b0 = *(const ulonglong2*)&Bs[k][tx * 8];
            ulonglong2 b1 = *(const ulonglong2*)&Bs[k][tx * 8 + 4];
            float av[8] = {a0.x, a0.y, a0.z, a0.w, a1.x, a1.y, a1.z, a1.w};
            unsigned long long bv[4] = {b0.x, b0.y, b1.x, b1.y};
            #pragma unroll
            for (int i = 0; i < 8; i++) {
                unsigned long long ad = pack_dup(av[i]);
                #pragma unroll
                for (int j = 0; j < 4; j++) fma2(acc[i][j], ad, bv[j]);
            }
        }
        __syncthreads();
    }

    #pragma unroll
    for (int i = 0; i < 8; i++) {
        int r = row0 + ty * 8 + i;
        if (r >= M) continue;
        #pragma unroll
        for (int j = 0; j < 4; j++) {
            int c = col0 + tx * 8 + j * 2;
            float x0, x1;
            unpack2(acc[i][j], x0, x1);
            x0 += bias[c];
            x1 += bias[c + 1];
            if (act) {
                x0 = x0 / (1.0f + expf(-x0));
                x1 = x1 / (1.0f + expf(-x1));
            }
            float2 o = make_float2(x0, x1);
            *(float2*)&C[(size_t)r * N + c] = o;
        }
    }
}

// ---------------------------------------------------------------------------
// Edge kernel v3: 4 channels/thread, 2 edges per iteration.
// 192 threads = 2 edge-groups x 96 channel-lanes. Each thread owns channels
// [4*lane .. 4*lane+3] of edge (2i + group). Per edge per thread:
//   5 sine LDS.128 (warp-broadcast) + 40 fma2 + 1 LDG.128 gather + 1 STG.128
// inv gather + meta software-prefetched one iteration ahead.
// ---------------------------------------------------------------------------
#define ETILE 192

__global__ __launch_bounds__(192) void edge_kernel(
    const float* __restrict__ dist,
    const int* __restrict__ nb,         // raw u32 words of nbrs
    const float* __restrict__ Wr,
    const float* __restrict__ br,
    const float* __restrict__ inv,
    float* __restrict__ out,
    int n_edges)
{
    __shared__ __align__(16) float  sm_s[ETILE][NRBF];  // sines
    __shared__ __align__(16) float4 sm_meta[ETILE];     // (k1, k2, j_bits, -)

    const int t    = threadIdx.x;
    const int grp  = (t >= 96) ? 1 : 0;
    const int lane = t - grp * 96;       // 0..95
    const int c0   = lane * 4;           // 4 channels
    const int is64 = g_nbrs_is64;

    // weight pairs for 4 channels: wrX[m] = (Wr[2m][c], Wr[2m+1][c])
    unsigned long long wrA[NRBF / 2], wrB[NRBF / 2];
    unsigned long long wrC[NRBF / 2], wrD[NRBF / 2];
    #pragma unroll
    for (int m = 0; m < NRBF / 2; m++) {
        float4 we = *(const float4*)&Wr[(2 * m)     * FEAT3 + c0];
        float4 wo = *(const float4*)&Wr[(2 * m + 1) * FEAT3 + c0];
        wrA[m] = pack2(we.x, wo.x);
        wrB[m] = pack2(we.y, wo.y);
        wrC[m] = pack2(we.z, wo.z);
        wrD[m] = pack2(we.w, wo.w);
    }
    const float4 brp = *(const float4*)&br[c0];

    const int base = blockIdx.x * ETILE;
    const int cnt  = min(ETILE, n_edges - base);

    // ---- phase A: one thread per edge --------------------------------------
    if (t < cnt) {
        const int e = base + t;
        const float d  = dist[e];
        const float th = d * 0.6283185307179586f;     // pi/5
        const float s1 = sinf(th);
        const float c1 = cosf(th);
        const float env = (d < 5.0f) ? 0.5f * (c1 + 1.0f) : 0.0f;
        const int   j   = is64 ? nb[4 * (long long)e + 2] : nb[2 * (long long)e + 1];
        sm_meta[t] = make_float4(env / d, env, __int_as_float(j), 0.0f);
        const float u = 2.0f * c1;
        float s[NRBF];
        float sp = 0.0f, sc = s1;
        #pragma unroll
        for (int n = 0; n < NRBF; n++) {
            s[n] = sc;
            float sn = fmaf(u, sc, -sp);
            sp = sc; sc = sn;
        }
        #pragma unroll
        for (int q = 0; q < NRBF / 4; q++)
            *(float4*)&sm_s[t][4 * q] =
                make_float4(s[4 * q], s[4 * q + 1], s[4 * q + 2], s[4 * q + 3]);
    }
    __syncthreads();

    // ---- phase B: each group sweeps edges grp, grp+2, grp+4, ... -----------
    int ei = grp;
    if (ei < cnt) {
        float4 meta = sm_meta[ei];
        float4 ph   = *(const float4*)&inv[(size_t)__float_as_int(meta.z) * FEAT3 + c0];

        while (ei < cnt) {
            // prefetch next edge for this group (clamped)
            const int en = (ei + 2 < cnt) ? (ei + 2) : ei;
            float4 meta_n = sm_meta[en];
            float4 ph_n   = *(const float4*)&inv[(size_t)__float_as_int(meta_n.z) * FEAT3 + c0];

            const ulonglong2* sr = (const ulonglong2*)sm_s[ei];

            unsigned long long aA = 0ull, aB = 0ull, aC = 0ull, aD = 0ull;
            #pragma unroll
            for (int q = 0; q < NRBF / 4; q++) {
                ulonglong2 sv = sr[q];   // LDS.128 broadcast: 4 sines
                fma2(aA, sv.x, wrA[2 * q]);
                fma2(aB, sv.x, wrB[2 * q]);
                fma2(aC, sv.x, wrC[2 * q]);
                fma2(aD, sv.x, wrD[2 * q]);
                fma2(aA, sv.y, wrA[2 * q + 1]);
                fma2(aB, sv.y, wrB[2 * q + 1]);
                fma2(aC, sv.y, wrC[2 * q + 1]);
                fma2(aD, sv.y, wrD[2 * q + 1]);
            }
            float lo, hi;
            unpack2(aA, lo, hi); const float dA = lo + hi;
            unpack2(aB, lo, hi); const float dB = lo + hi;
            unpack2(aC, lo, hi); const float dC = lo + hi;
            unpack2(aD, lo, hi); const float dD = lo + hi;

            const float k1 = meta.x, k2 = meta.y;
            float4 o;
            o.x = fmaf(dA, k1, brp.x * k2) * ph.x;
            o.y = fmaf(dB, k1, brp.y * k2) * ph.y;
            o.z = fmaf(dC, k1, brp.z * k2) * ph.z;
            o.w = fmaf(dD, k1, brp.w * k2) * ph.w;
            *(float4*)&out[(size_t)(base + ei) * FEAT3 + c0] = o;

            meta = meta_n;
            ph   = ph_n;
            ei  += 2;
        }
    }
}

// ---------------------------------------------------------------------------
// kernel_launch
// ---------------------------------------------------------------------------
extern "C" void kernel_launch(void* const* d_in, const int* in_sizes, int n_in,
                              void* d_out, int out_size)
{
    const float* s_j  = (const float*)d_in[0];
    const float* dist = (const float*)d_in[1];
    const int*   nb   = (const int*)  d_in[2];
    const float* W1   = (const float*)d_in[3];
    const float* b1   = (const float*)d_in[4];
    const float* W2   = (const float*)d_in[5];
    const float* b2   = (const float*)d_in[6];
    const float* Wr   = (const float*)d_in[7];
    const float* br   = (const float*)d_in[8];
    float*       out  = (float*)d_out;

    const int n_nodes = in_sizes[0] / FEAT;
    const int n_edges = in_sizes[1];

    float* hbuf;
    float* invbuf;
    cudaGetSymbolAddress((void**)&hbuf,   g_h);
    cudaGetSymbolAddress((void**)&invbuf, g_inv);

    detect_nbrs_kernel<<<1, 32>>>((const unsigned int*)nb, in_sizes[2]);

    // GEMM1: h = silu(s_j @ W1 + b1)
    {
        dim3 grid((n_nodes + BM - 1) / BM, 1);
        sgemm_kernel<<<grid, 256>>>(s_j, W1, b1, hbuf,
                                    n_nodes, FEAT, FEAT, /*act=*/1);
    }
    // GEMM2: inv = h @ W2 + b2
    {
        dim3 grid((n_nodes + BM - 1) / BM, FEAT3 / BN);
        sgemm_kernel<<<grid, 256>>>(hbuf, W2, b2, invbuf,
                                    n_nodes, FEAT3, FEAT, /*act=*/0);
    }
    // Edge kernel
    {
        dim3 grid((n_edges + ETILE - 1) / ETILE);
        edge_kernel<<<grid, ETILE>>>(dist, nb, Wr, br, invbuf, out, n_edges);
    }
}